// round 12
// baseline (speedup 1.0000x reference)
#include <cuda_runtime.h>
#include <math.h>

#define BATCH   16
#define D_IN    1024
#define T_IN    4096
#define CB_SIZE 8192
#define CB_DIM  512
#define T1      2048
#define T2      1024
#define NTOK    (BATCH * T2)
#define NSPLIT  8
#define NTILES  8
#define NSLOT   (NSPLIT * NTILES)

// Scratch — referenced only from device code.
__device__ float g_y1 [BATCH * CB_DIM * T1];   // 64 MB conv1 out [b][co][t]
__device__ float g_y2 [BATCH * CB_DIM * T2];   // 32 MB conv2 out [b][co][t]
__device__ float g_cbT[CB_DIM * CB_SIZE];      // 16 MB normalized codebook [d][code]
__device__ float g_inorm[CB_SIZE];
__device__ float g_pv[(size_t)NTOK * NSLOT];
__device__ int   g_pi[(size_t)NTOK * NSLOT];

// ---------------- codebook inverse norms ----------------
__global__ void __launch_bounds__(128) norm_kernel(const float* __restrict__ cb) {
    __shared__ float red[4];
    int row = blockIdx.x;
    const float* r = cb + (size_t)row * CB_DIM;
    float s = 0.f;
    for (int i = threadIdx.x; i < CB_DIM; i += 128) { float v = r[i]; s += v * v; }
    #pragma unroll
    for (int o = 16; o; o >>= 1) s += __shfl_down_sync(0xffffffffu, s, o);
    if ((threadIdx.x & 31) == 0) red[threadIdx.x >> 5] = s;
    __syncthreads();
    if (threadIdx.x == 0) {
        float t = red[0] + red[1] + red[2] + red[3];
        g_inorm[row] = 1.f / fmaxf(sqrtf(t), 1e-12f);
    }
}

// ---------------- normalize + transpose codebook -> g_cbT[d][code] ----------------
__global__ void __launch_bounds__(256) transpose_norm_kernel(const float* __restrict__ cb) {
    __shared__ float tile[32][33];
    int r0 = blockIdx.x * 32;
    int d0 = blockIdx.y * 32;
    int tx = threadIdx.x;
    int ty = threadIdx.y;
    #pragma unroll
    for (int i = ty; i < 32; i += 8)
        tile[i][tx] = cb[(size_t)(r0 + i) * CB_DIM + d0 + tx] * g_inorm[r0 + i];
    __syncthreads();
    #pragma unroll
    for (int i = ty; i < 32; i += 8)
        g_cbT[(size_t)(d0 + i) * CB_SIZE + r0 + tx] = tile[tx][i];
}

// ---------------- stride-2 conv1d (k=3, pad=1), 128x128 tile, 8x8 micro, CHUNK=16 ----------------
// Phase-split X smem; split fragments (16B lane stride, conflict-free).
// Accumulation order (ci,k ascending) identical to prior rounds -> bitwise-same results.
template <int CIN, int TIN, int STAGE>
__global__ void __launch_bounds__(256, 2) conv_s2_kernel(const float* __restrict__ xin,
                                                         const float* __restrict__ W) {
    constexpr int TOUT = TIN / 2;
    const float* X = (STAGE == 0) ? xin : (const float*)g_y1;
    float*       Y = (STAGE == 0) ? g_y1 : g_y2;

    __shared__ float Wt[48][132];   // [ci*3+k][co], ci-chunk 16
    __shared__ float Xe[16][128];   // even phase
    __shared__ float Xo[16][132];   // odd phase, 129 used

    int t0  = blockIdx.x * 128;
    int co0 = blockIdx.y * 128;
    int b   = blockIdx.z;
    int tid = threadIdx.x;
    int tx  = tid & 15;    // t dir
    int ty  = tid >> 4;    // co dir

    float acc[8][8];
    #pragma unroll
    for (int i = 0; i < 8; i++)
        #pragma unroll
        for (int j = 0; j < 8; j++) acc[i][j] = 0.f;

    const float* Xb = X + (size_t)b * CIN * TIN;

    for (int c0 = 0; c0 < CIN; c0 += 16) {
        // ---- weights: 128 co x 48 floats -> transposed smem (6 float4/thread)
        #pragma unroll
        for (int s = 0; s < 6; s++) {
            int f  = tid + s * 256;
            int co = f / 12, q = f % 12;
            float4 w4 = *(const float4*)(W + (size_t)(co0 + co) * (CIN * 3) + c0 * 3 + q * 4);
            Wt[q * 4 + 0][co] = w4.x;
            Wt[q * 4 + 1][co] = w4.y;
            Wt[q * 4 + 2][co] = w4.z;
            Wt[q * 4 + 3][co] = w4.w;
        }
        // ---- x: 16 ci x 256 inputs, float4 loads, even/odd scatter (4 float4/thread)
        #pragma unroll
        for (int s = 0; s < 4; s++) {
            int f  = tid + s * 256;
            int ci = f >> 6, u = f & 63;
            float4 x4 = *(const float4*)(Xb + (size_t)(c0 + ci) * TIN + 2 * t0 + u * 4);
            Xe[ci][2 * u]     = x4.x;
            Xo[ci][2 * u + 1] = x4.y;
            Xe[ci][2 * u + 1] = x4.z;
            Xo[ci][2 * u + 2] = x4.w;
        }
        if (tid < 16) {
            float v = 0.f;
            if (t0 > 0) v = Xb[(size_t)(c0 + tid) * TIN + 2 * t0 - 1];
            Xo[tid][0] = v;
        }
        __syncthreads();

        #pragma unroll
        for (int ci = 0; ci < 16; ci++) {
            float xe[8], xoA[5], xoB[5];
            *(float4*)&xe[0]  = *(const float4*)&Xe[ci][tx * 4];
            *(float4*)&xe[4]  = *(const float4*)&Xe[ci][64 + tx * 4];
            *(float4*)&xoA[0] = *(const float4*)&Xo[ci][tx * 4];
            xoA[4] = Xo[ci][tx * 4 + 4];
            *(float4*)&xoB[0] = *(const float4*)&Xo[ci][64 + tx * 4];
            xoB[4] = Xo[ci][64 + tx * 4 + 4];
            #pragma unroll
            for (int k = 0; k < 3; k++) {
                float av[8];
                *(float4*)&av[0] = *(const float4*)&Wt[ci * 3 + k][ty * 4];
                *(float4*)&av[4] = *(const float4*)&Wt[ci * 3 + k][64 + ty * 4];
                #pragma unroll
                for (int i = 0; i < 8; i++)
                    #pragma unroll
                    for (int j = 0; j < 8; j++) {
                        float xv = (j < 4)
                            ? ((k == 0) ? xoA[j] : (k == 1) ? xe[j] : xoA[j + 1])
                            : ((k == 0) ? xoB[j - 4] : (k == 1) ? xe[j] : xoB[j - 3]);
                        acc[i][j] = fmaf(av[i], xv, acc[i][j]);
                    }
            }
        }
        __syncthreads();
    }

    #pragma unroll
    for (int i = 0; i < 8; i++) {
        int co = co0 + ((i < 4) ? (ty * 4 + i) : (64 + ty * 4 + i - 4));
        float* yr = Y + ((size_t)b * 512 + co) * TOUT + t0;
        *(float4*)(yr + tx * 4)      = make_float4(acc[i][0], acc[i][1], acc[i][2], acc[i][3]);
        *(float4*)(yr + 64 + tx * 4) = make_float4(acc[i][4], acc[i][5], acc[i][6], acc[i][7]);
    }
}

// ---------------- scoring GEMM: 128 tok x 128 codes, split-fragment 8x8, K-chunk 16 ----------------
__global__ void __launch_bounds__(256, 2) score_kernel() {
    __shared__ float Es[2][16][128];
    __shared__ float Cs[2][16][128];

    int split = blockIdx.x;
    int ttile = blockIdx.y;
    int b  = ttile >> 3;
    int t0 = (ttile & 7) * 128;
    int tid = threadIdx.x;
    int ty  = tid >> 4;
    int tx  = tid & 15;

    const float* Ybase = g_y2 + (size_t)b * CB_DIM * T2 + t0;

    for (int nt = 0; nt < NTILES; nt++) {
        int n0 = split * (NTILES * 128) + nt * 128;

        float acc[8][8];
        #pragma unroll
        for (int i = 0; i < 8; i++)
            #pragma unroll
            for (int j = 0; j < 8; j++) acc[i][j] = 0.f;

        // preload chunk 0: 16 rows x 32 float4 -> 2 float4/thread each for Es, Cs
        #pragma unroll
        for (int s = 0; s < 2; s++) {
            int f  = tid + s * 256;
            int kk = f >> 5, m = f & 31;
            *(float4*)&Es[0][kk][m * 4] =
                *(const float4*)(Ybase + (size_t)kk * T2 + m * 4);
            *(float4*)&Cs[0][kk][m * 4] =
                *(const float4*)(g_cbT + (size_t)kk * CB_SIZE + n0 + m * 4);
        }
        __syncthreads();

        int buf = 0;
        for (int k0 = 0; k0 < CB_DIM; k0 += 16) {
            if (k0 + 16 < CB_DIM) {
                #pragma unroll
                for (int s = 0; s < 2; s++) {
                    int f  = tid + s * 256;
                    int kk = f >> 5, m = f & 31;
                    *(float4*)&Es[buf ^ 1][kk][m * 4] =
                        *(const float4*)(Ybase + (size_t)(k0 + 16 + kk) * T2 + m * 4);
                    *(float4*)&Cs[buf ^ 1][kk][m * 4] =
                        *(const float4*)(g_cbT + (size_t)(k0 + 16 + kk) * CB_SIZE + n0 + m * 4);
                }
            }
            #pragma unroll
            for (int kk = 0; kk < 16; kk++) {
                float a[8], c[8];
                *(float4*)&a[0] = *(const float4*)&Es[buf][kk][ty * 4];
                *(float4*)&a[4] = *(const float4*)&Es[buf][kk][64 + ty * 4];
                *(float4*)&c[0] = *(const float4*)&Cs[buf][kk][tx * 4];
                *(float4*)&c[4] = *(const float4*)&Cs[buf][kk][64 + tx * 4];
                #pragma unroll
                for (int i = 0; i < 8; i++)
                    #pragma unroll
                    for (int j = 0; j < 8; j++)
                        acc[i][j] = fmaf(a[i], c[j], acc[i][j]);
            }
            __syncthreads();
            buf ^= 1;
        }

        #pragma unroll
        for (int i = 0; i < 8; i++) {
            float bvv = -3.4e38f; int bii = 0x7fffffff;
            #pragma unroll
            for (int j = 0; j < 8; j++) {
                int n = n0 + ((j < 4) ? (tx * 4 + j) : (64 + tx * 4 + j - 4));
                float v = acc[i][j];
                if (v > bvv) { bvv = v; bii = n; }     // n ascending in j
            }
            #pragma unroll
            for (int off = 8; off > 0; off >>= 1) {
                float ov = __shfl_xor_sync(0xffffffffu, bvv, off);
                int   oi = __shfl_xor_sync(0xffffffffu, bii, off);
                if (ov > bvv || (ov == bvv && oi < bii)) { bvv = ov; bii = oi; }
            }
            if (tx == 0) {
                int tok_local = (i < 4) ? (ty * 4 + i) : (64 + ty * 4 + i - 4);
                int token = ttile * 128 + tok_local;
                int slot  = split * NTILES + nt;
                g_pv[(size_t)token * NSLOT + slot] = bvv;
                g_pi[(size_t)token * NSLOT + slot] = bii;
            }
        }
        __syncthreads();
    }
}

// ---------------- combine partials -> float index output ----------------
__global__ void __launch_bounds__(256) finalize_kernel(float* __restrict__ out) {
    int token = blockIdx.x * 256 + threadIdx.x;
    if (token >= NTOK) return;
    const float* pv = g_pv + (size_t)token * NSLOT;
    const int*   pi = g_pi + (size_t)token * NSLOT;
    float bv = -3.4e38f; int bi = 0x7fffffff;
    for (int s = 0; s < NSLOT; s++) {
        float v = pv[s]; int idx = pi[s];
        if (v > bv || (v == bv && idx < bi)) { bv = v; bi = idx; }
    }
    out[token] = (float)bi;
}

extern "C" void kernel_launch(void* const* d_in, const int* in_sizes, int n_in,
                              void* d_out, int out_size) {
    const float *x = 0, *w1 = 0, *w2 = 0, *cb = 0;
    for (int i = 0; i < n_in; i++) {
        switch (in_sizes[i]) {
            case BATCH * D_IN * T_IN:   x  = (const float*)d_in[i]; break;
            case CB_DIM * D_IN * 3:     w1 = (const float*)d_in[i]; break;
            case CB_DIM * CB_DIM * 3:   w2 = (const float*)d_in[i]; break;
            case CB_SIZE * CB_DIM:      cb = (const float*)d_in[i]; break;
        }
    }
    if (!x || !w1 || !w2 || !cb) {
        x  = (const float*)d_in[0];
        w1 = (const float*)d_in[1];
        w2 = (const float*)d_in[2];
        cb = (const float*)d_in[3];
    }

    norm_kernel<<<CB_SIZE, 128>>>(cb);
    transpose_norm_kernel<<<dim3(CB_SIZE / 32, CB_DIM / 32), dim3(32, 8)>>>(cb);

    conv_s2_kernel<D_IN, T_IN, 0><<<dim3(T_IN / 256, 4, BATCH), 256>>>(x, w1);
    conv_s2_kernel<CB_DIM, T1, 1><<<dim3(T1 / 256, 4, BATCH), 256>>>(nullptr, w2);

    score_kernel<<<dim3(NSPLIT, 128), 256>>>();
    finalize_kernel<<<(NTOK + 255) / 256, 256>>>((float*)d_out);
}

// round 14
// speedup vs baseline: 1.6156x; 1.6156x over previous
#include <cuda_runtime.h>
#include <cuda_bf16.h>
#include <math.h>
#include <cstdint>

#define BATCH   16
#define D_IN    1024
#define T_IN    4096
#define CB_SIZE 8192
#define CB_DIM  512
#define T1      2048
#define T2      1024
#define NTOK    (BATCH * T2)

// ---------------- scratch (device-code references only) ----------------
__device__ float          g_y1     [BATCH * CB_DIM * T1];      // 64 MB conv1 out [b][co][t]
__device__ float          g_encT   [(size_t)NTOK * CB_DIM];    // 32 MB enc fp32 [tok][d]
__device__ __nv_bfloat16  g_enc_bf [(size_t)NTOK * CB_DIM];    // 16 MB enc bf16 [tok][d]
__device__ float          g_cb_nrm [(size_t)CB_SIZE * CB_DIM]; // 16 MB normalized cb fp32
__device__ __nv_bfloat16  g_cb_bf  [(size_t)CB_SIZE * CB_DIM]; //  8 MB normalized cb bf16
__device__ int            g_cand   [NTOK * 8];                 // 8 candidates per token

__device__ __forceinline__ uint32_t smem_u32(const void* p) {
    uint32_t a;
    asm("{ .reg .u64 t; cvta.to.shared.u64 t, %1; cvt.u32.u64 %0, t; }" : "=r"(a) : "l"(p));
    return a;
}
__device__ __forceinline__ bool better(float va, int ia, float vb, int ib) {
    return va > vb || (va == vb && ia < ib);
}
__device__ __forceinline__ void ins4(float v, int i, float* tv, int* ti) {
    if (!better(v, i, tv[3], ti[3])) return;
    int p = 3;
    if (better(v, i, tv[0], ti[0])) p = 0;
    else if (better(v, i, tv[1], ti[1])) p = 1;
    else if (better(v, i, tv[2], ti[2])) p = 2;
    for (int s = 3; s > p; s--) { tv[s] = tv[s - 1]; ti[s] = ti[s - 1]; }
    tv[p] = v; ti[p] = i;
}

// ---------------- codebook: normalize -> fp32 + bf16 ----------------
__global__ void __launch_bounds__(128) cb_norm_kernel(const float* __restrict__ cb) {
    __shared__ float red[4];
    int row = blockIdx.x, tid = threadIdx.x;
    const float* r = cb + (size_t)row * CB_DIM;
    float s = 0.f;
    for (int i = tid; i < CB_DIM; i += 128) { float v = r[i]; s += v * v; }
    #pragma unroll
    for (int o = 16; o; o >>= 1) s += __shfl_down_sync(0xffffffffu, s, o);
    if ((tid & 31) == 0) red[tid >> 5] = s;
    __syncthreads();
    float inv = 1.f / fmaxf(sqrtf(red[0] + red[1] + red[2] + red[3]), 1e-12f);
    for (int i = tid; i < CB_DIM; i += 128) {
        float v = r[i] * inv;
        g_cb_nrm[(size_t)row * CB_DIM + i] = v;
        g_cb_bf [(size_t)row * CB_DIM + i] = __float2bfloat16_rn(v);
    }
}

// ---------------- stride-2 conv1d (k=3,pad=1), R11 champion config ----------------
template <int CIN, int TIN, int STAGE>
__global__ void __launch_bounds__(256, 2) conv_s2_kernel(const float* __restrict__ xin,
                                                         const float* __restrict__ W) {
    constexpr int TOUT = TIN / 2;
    const float* X = (STAGE == 0) ? xin : (const float*)g_y1;

    __shared__ float Wt[24][132];
    __shared__ float Xe[8][128];
    __shared__ float Xo[8][132];

    int t0  = blockIdx.x * 128;
    int co0 = blockIdx.y * 128;
    int b   = blockIdx.z;
    int tid = threadIdx.x;
    int tx  = tid & 15;
    int ty  = tid >> 4;

    float acc[8][8];
    #pragma unroll
    for (int i = 0; i < 8; i++)
        #pragma unroll
        for (int j = 0; j < 8; j++) acc[i][j] = 0.f;

    const float* Xb = X + (size_t)b * CIN * TIN;

    for (int c0 = 0; c0 < CIN; c0 += 8) {
        #pragma unroll
        for (int s = 0; s < 3; s++) {
            int f = tid + s * 256;
            int co = f / 6, q = f % 6;
            float4 w4 = *(const float4*)(W + (size_t)(co0 + co) * (CIN * 3) + c0 * 3 + q * 4);
            Wt[q * 4 + 0][co] = w4.x; Wt[q * 4 + 1][co] = w4.y;
            Wt[q * 4 + 2][co] = w4.z; Wt[q * 4 + 3][co] = w4.w;
        }
        #pragma unroll
        for (int s = 0; s < 2; s++) {
            int f = tid + s * 256;
            int ci = f >> 6, u = f & 63;
            float4 x4 = *(const float4*)(Xb + (size_t)(c0 + ci) * TIN + 2 * t0 + u * 4);
            Xe[ci][2 * u] = x4.x; Xo[ci][2 * u + 1] = x4.y;
            Xe[ci][2 * u + 1] = x4.z; Xo[ci][2 * u + 2] = x4.w;
        }
        if (tid < 8) {
            float v = 0.f;
            if (t0 > 0) v = Xb[(size_t)(c0 + tid) * TIN + 2 * t0 - 1];
            Xo[tid][0] = v;
        }
        __syncthreads();

        #pragma unroll
        for (int ci = 0; ci < 8; ci++) {
            float xe[8], xoA[5], xoB[5];
            *(float4*)&xe[0]  = *(const float4*)&Xe[ci][tx * 4];
            *(float4*)&xe[4]  = *(const float4*)&Xe[ci][64 + tx * 4];
            *(float4*)&xoA[0] = *(const float4*)&Xo[ci][tx * 4];
            xoA[4] = Xo[ci][tx * 4 + 4];
            *(float4*)&xoB[0] = *(const float4*)&Xo[ci][64 + tx * 4];
            xoB[4] = Xo[ci][64 + tx * 4 + 4];
            #pragma unroll
            for (int k = 0; k < 3; k++) {
                float av[8];
                *(float4*)&av[0] = *(const float4*)&Wt[ci * 3 + k][ty * 4];
                *(float4*)&av[4] = *(const float4*)&Wt[ci * 3 + k][64 + ty * 4];
                #pragma unroll
                for (int i = 0; i < 8; i++)
                    #pragma unroll
                    for (int j = 0; j < 8; j++) {
                        float xv = (j < 4)
                            ? ((k == 0) ? xoA[j] : (k == 1) ? xe[j] : xoA[j + 1])
                            : ((k == 0) ? xoB[j - 4] : (k == 1) ? xe[j] : xoB[j - 3]);
                        acc[i][j] = fmaf(av[i], xv, acc[i][j]);
                    }
            }
        }
        __syncthreads();
    }

    if (STAGE == 0) {
        #pragma unroll
        for (int i = 0; i < 8; i++) {
            int co = co0 + ((i < 4) ? (ty * 4 + i) : (64 + ty * 4 + i - 4));
            float* yr = g_y1 + ((size_t)b * 512 + co) * TOUT + t0;
            *(float4*)(yr + tx * 4)      = make_float4(acc[i][0], acc[i][1], acc[i][2], acc[i][3]);
            *(float4*)(yr + 64 + tx * 4) = make_float4(acc[i][4], acc[i][5], acc[i][6], acc[i][7]);
        }
    } else {
        #pragma unroll
        for (int j = 0; j < 8; j++) {
            int tok = b * TOUT + t0 + ((j < 4) ? (tx * 4 + j) : (64 + tx * 4 + j - 4));
            #pragma unroll
            for (int h = 0; h < 2; h++) {
                int d = co0 + h * 64 + ty * 4;
                float v0 = acc[h * 4 + 0][j], v1 = acc[h * 4 + 1][j];
                float v2 = acc[h * 4 + 2][j], v3 = acc[h * 4 + 3][j];
                *(float4*)(g_encT + (size_t)tok * CB_DIM + d) = make_float4(v0, v1, v2, v3);
                *(__nv_bfloat162*)(g_enc_bf + (size_t)tok * CB_DIM + d)     = __floats2bfloat162_rn(v0, v1);
                *(__nv_bfloat162*)(g_enc_bf + (size_t)tok * CB_DIM + d + 2) = __floats2bfloat162_rn(v2, v3);
            }
        }
    }
}

// ---------------- bf16 mma.sync scoring + register-resident top-4 ----------------
// Block: 64 tokens, 256 threads (8 warps = 4 m-groups x 2 n-halves).
// A smem: [64][520] bf16 (resident); B smem: double-buffered [128][40] bf16 chunks.
#define A_LD   520
#define B_LD   40
#define SCORE_SMEM ((64 * A_LD + 2 * 128 * B_LD) * 2)

__global__ void __launch_bounds__(256) score_mma_kernel() {
    extern __shared__ __align__(16) __nv_bfloat16 sm[];
    __nv_bfloat16* As = sm;                    // [64][520]
    __nv_bfloat16* Bs = sm + 64 * A_LD;        // [2][128][40]

    int tid = threadIdx.x;
    int warp = tid >> 5, lane = tid & 31;
    int warp_m = warp >> 1;        // 0..3 -> token rows mt = warp_m*16
    int warp_n = warp & 1;         // 0..1 -> code half wn0 = warp_n*64
    int mt  = warp_m * 16;
    int wn0 = warp_n * 64;
    int g = lane >> 2, tg = lane & 3;
    int tok0 = blockIdx.x * 64;

    uint32_t as_base = smem_u32(As);
    uint32_t bs_base = smem_u32(Bs);

    // load A: 64 tokens x 512 bf16 (64 uint4 per row)
    #pragma unroll
    for (int s = 0; s < 16; s++) {
        int f = tid + s * 256;                 // 0..4095
        int t = f >> 6, q = f & 63;
        *(uint4*)(As + t * A_LD + q * 8) =
            ((const uint4*)(g_enc_bf + (size_t)(tok0 + t) * CB_DIM))[q];
    }
    __syncthreads();

    // ldmatrix lane addresses (element offsets precomputed per lane)
    uint32_t a_row = (uint32_t)(mt + (lane & 15));
    uint32_t a_koff = (uint32_t)((lane >> 4) << 3);
    uint32_t b_code_off = (uint32_t)(((lane >> 4) << 3) + (lane & 7));
    uint32_t b_koff = (uint32_t)(((lane >> 3) & 1) << 3);

    float tv0[4] = {-3.4e38f, -3.4e38f, -3.4e38f, -3.4e38f};
    float tv1[4] = {-3.4e38f, -3.4e38f, -3.4e38f, -3.4e38f};
    int   ti0[4] = {0x7fffffff, 0x7fffffff, 0x7fffffff, 0x7fffffff};
    int   ti1[4] = {0x7fffffff, 0x7fffffff, 0x7fffffff, 0x7fffffff};

    for (int ntile = 0; ntile < CB_SIZE / 128; ntile++) {
        int n0 = ntile * 128;

        float c[8][4];
        #pragma unroll
        for (int na = 0; na < 8; na++)
            #pragma unroll
            for (int r = 0; r < 4; r++) c[na][r] = 0.f;

        // preload chunk 0 (k 0..31 for 128 codes)
        #pragma unroll
        for (int s = 0; s < 2; s++) {
            int f = tid + s * 256;
            int code = f >> 2, q = f & 3;
            *(uint4*)(Bs + code * B_LD + q * 8) =
                ((const uint4*)(g_cb_bf + (size_t)(n0 + code) * CB_DIM))[q];
        }
        __syncthreads();

        for (int kc = 0; kc < 16; kc++) {
            int buf = kc & 1;
            if (kc + 1 < 16) {
                #pragma unroll
                for (int s = 0; s < 2; s++) {
                    int f = tid + s * 256;
                    int code = f >> 2, q = f & 3;
                    *(uint4*)(Bs + (buf ^ 1) * 128 * B_LD + code * B_LD + q * 8) =
                        ((const uint4*)(g_cb_bf + (size_t)(n0 + code) * CB_DIM + (kc + 1) * 32))[q];
                }
            }
            uint32_t bbuf = bs_base + (uint32_t)(buf * 128 * B_LD) * 2u;
            #pragma unroll
            for (int ks = 0; ks < 2; ks++) {
                int kb = kc * 32 + ks * 16;
                uint32_t a0, a1, a2, a3;
                uint32_t a_addr = as_base + (a_row * A_LD + (uint32_t)kb + a_koff) * 2u;
                asm volatile("ldmatrix.sync.aligned.m8n8.x4.shared.b16 {%0,%1,%2,%3}, [%4];"
                             : "=r"(a0), "=r"(a1), "=r"(a2), "=r"(a3) : "r"(a_addr));
                #pragma unroll
                for (int pa = 0; pa < 4; pa++) {
                    uint32_t b0, b1, b2, b3;
                    uint32_t code = (uint32_t)(wn0 + pa * 16) + b_code_off;
                    uint32_t b_addr = bbuf + (code * B_LD + (uint32_t)(ks * 16) + b_koff) * 2u;
                    asm volatile("ldmatrix.sync.aligned.m8n8.x4.shared.b16 {%0,%1,%2,%3}, [%4];"
                                 : "=r"(b0), "=r"(b1), "=r"(b2), "=r"(b3) : "r"(b_addr));
                    asm volatile("mma.sync.aligned.m16n8k16.row.col.f32.bf16.bf16.f32 "
                                 "{%0,%1,%2,%3}, {%4,%5,%6,%7}, {%8,%9}, {%0,%1,%2,%3};"
                                 : "+f"(c[pa * 2][0]), "+f"(c[pa * 2][1]),
                                   "+f"(c[pa * 2][2]), "+f"(c[pa * 2][3])
                                 : "r"(a0), "r"(a1), "r"(a2), "r"(a3), "r"(b0), "r"(b1));
                    asm volatile("mma.sync.aligned.m16n8k16.row.col.f32.bf16.bf16.f32 "
                                 "{%0,%1,%2,%3}, {%4,%5,%6,%7}, {%8,%9}, {%0,%1,%2,%3};"
                                 : "+f"(c[pa * 2 + 1][0]), "+f"(c[pa * 2 + 1][1]),
                                   "+f"(c[pa * 2 + 1][2]), "+f"(c[pa * 2 + 1][3])
                                 : "r"(a0), "r"(a1), "r"(a2), "r"(a3), "r"(b2), "r"(b3));
                }
            }
            __syncthreads();
        }

        // extract per-row top-2 of this 64-code half-tile, merge across the quad
        #pragma unroll
        for (int r = 0; r < 2; r++) {
            float m1 = -3.4e38f, m2 = -3.4e38f;
            int   i1 = 0x7fffffff, i2 = 0x7fffffff;
            #pragma unroll
            for (int na = 0; na < 8; na++) {
                #pragma unroll
                for (int j = 0; j < 2; j++) {
                    float v = c[na][r * 2 + j];
                    int idx = n0 + wn0 + na * 8 + tg * 2 + j;
                    if (v > m1) { m2 = m1; i2 = i1; m1 = v; i1 = idx; }
                    else if (v > m2) { m2 = v; i2 = idx; }
                }
            }
            #pragma unroll
            for (int off = 1; off <= 2; off <<= 1) {
                float om1 = __shfl_xor_sync(0xffffffffu, m1, off);
                int   oi1 = __shfl_xor_sync(0xffffffffu, i1, off);
                float om2 = __shfl_xor_sync(0xffffffffu, m2, off);
                int   oi2 = __shfl_xor_sync(0xffffffffu, i2, off);
                if (better(om1, oi1, m1, i1)) {
                    m2 = m1; i2 = i1;
                    if (better(om2, oi2, m2, i2)) { m2 = om2; i2 = oi2; }
                    m1 = om1; i1 = oi1;
                } else if (better(om1, oi1, m2, i2)) { m2 = om1; i2 = oi1; }
            }
            if (r == 0) { ins4(m1, i1, tv0, ti0); ins4(m2, i2, tv0, ti0); }
            else        { ins4(m1, i1, tv1, ti1); ins4(m2, i2, tv1, ti1); }
        }
    }

    if (tg == 0) {
        int token0 = tok0 + mt + g;
        int token1 = token0 + 8;
        #pragma unroll
        for (int s = 0; s < 4; s++) {
            g_cand[token0 * 8 + warp_n * 4 + s] = ti0[s];
            g_cand[token1 * 8 + warp_n * 4 + s] = ti1[s];
        }
    }
}

// ---------------- exact fp32 rescue over 8 candidates ----------------
__global__ void __launch_bounds__(256) rescue_kernel(float* __restrict__ out) {
    int token = blockIdx.x * 8 + (threadIdx.x >> 5);
    int lane  = threadIdx.x & 31;
    if (token >= NTOK) return;

    const float4* e = (const float4*)(g_encT + (size_t)token * CB_DIM);
    float bestv = -3.4e38f; int besti = 0x7fffffff;
    #pragma unroll
    for (int c = 0; c < 8; c++) {
        int idx = g_cand[token * 8 + c];
        if ((unsigned)idx >= CB_SIZE) continue;
        const float4* cr = (const float4*)(g_cb_nrm + (size_t)idx * CB_DIM);
        float s = 0.f;
        #pragma unroll
        for (int i = 0; i < 4; i++) {
            float4 ev = e[lane + i * 32];
            float4 cv = cr[lane + i * 32];
            s += ev.x * cv.x + ev.y * cv.y + ev.z * cv.z + ev.w * cv.w;
        }
        #pragma unroll
        for (int o = 16; o; o >>= 1) s += __shfl_xor_sync(0xffffffffu, s, o);
        if (s > bestv || (s == bestv && idx < besti)) { bestv = s; besti = idx; }
    }
    if (lane == 0) out[token] = (float)besti;
}

extern "C" void kernel_launch(void* const* d_in, const int* in_sizes, int n_in,
                              void* d_out, int out_size) {
    const float *x = 0, *w1 = 0, *w2 = 0, *cb = 0;
    for (int i = 0; i < n_in; i++) {
        switch (in_sizes[i]) {
            case BATCH * D_IN * T_IN:   x  = (const float*)d_in[i]; break;
            case CB_DIM * D_IN * 3:     w1 = (const float*)d_in[i]; break;
            case CB_DIM * CB_DIM * 3:   w2 = (const float*)d_in[i]; break;
            case CB_SIZE * CB_DIM:      cb = (const float*)d_in[i]; break;
        }
    }
    if (!x || !w1 || !w2 || !cb) {
        x  = (const float*)d_in[0];
        w1 = (const float*)d_in[1];
        w2 = (const float*)d_in[2];
        cb = (const float*)d_in[3];
    }

    cudaFuncSetAttribute(score_mma_kernel,
                         cudaFuncAttributeMaxDynamicSharedMemorySize, SCORE_SMEM);

    cb_norm_kernel<<<CB_SIZE, 128>>>(cb);
    conv_s2_kernel<D_IN, T_IN, 0><<<dim3(T_IN / 256, 4, BATCH), 256>>>(x, w1);
    conv_s2_kernel<CB_DIM, T1, 1><<<dim3(T1 / 256, 4, BATCH), 256>>>(nullptr, w2);
    score_mma_kernel<<<NTOK / 64, 256, SCORE_SMEM>>>();
    rescue_kernel<<<(NTOK + 7) / 8, 256>>>((float*)d_out);
}

// round 15
// speedup vs baseline: 1.6573x; 1.0258x over previous
#include <cuda_runtime.h>
#include <cuda_bf16.h>
#include <math.h>
#include <cstdint>

#define BATCH   16
#define D_IN    1024
#define T_IN    4096
#define CB_SIZE 8192
#define CB_DIM  512
#define T1      2048
#define T2      1024
#define NTOK    (BATCH * T2)

// ---------------- scratch (device-code references only) ----------------
__device__ float          g_y1     [BATCH * CB_DIM * T1];      // 64 MB conv1 out [b][co][t]
__device__ float          g_encT   [(size_t)NTOK * CB_DIM];    // 32 MB enc fp32 [tok][d]
__device__ __nv_bfloat16  g_enc_bf [(size_t)NTOK * CB_DIM];    // 16 MB enc bf16 [tok][d]
__device__ float          g_cb_nrm [(size_t)CB_SIZE * CB_DIM]; // 16 MB normalized cb fp32
__device__ __nv_bfloat16  g_cb_bf  [(size_t)CB_SIZE * CB_DIM]; //  8 MB normalized cb bf16
__device__ int            g_cand   [NTOK * 8];                 // 8 candidates per token

__device__ __forceinline__ uint32_t smem_u32(const void* p) {
    uint32_t a;
    asm("{ .reg .u64 t; cvta.to.shared.u64 t, %1; cvt.u32.u64 %0, t; }" : "=r"(a) : "l"(p));
    return a;
}
__device__ __forceinline__ void cp_async16(uint32_t dst, const void* src) {
    asm volatile("cp.async.cg.shared.global [%0], [%1], 16;" :: "r"(dst), "l"(src));
}
__device__ __forceinline__ bool better(float va, int ia, float vb, int ib) {
    return va > vb || (va == vb && ia < ib);
}
__device__ __forceinline__ void ins4(float v, int i, float* tv, int* ti) {
    if (!better(v, i, tv[3], ti[3])) return;
    int p = 3;
    if (better(v, i, tv[0], ti[0])) p = 0;
    else if (better(v, i, tv[1], ti[1])) p = 1;
    else if (better(v, i, tv[2], ti[2])) p = 2;
    for (int s = 3; s > p; s--) { tv[s] = tv[s - 1]; ti[s] = ti[s - 1]; }
    tv[p] = v; ti[p] = i;
}

// ---------------- codebook: normalize -> fp32 + bf16 ----------------
__global__ void __launch_bounds__(128) cb_norm_kernel(const float* __restrict__ cb) {
    __shared__ float red[4];
    int row = blockIdx.x, tid = threadIdx.x;
    const float* r = cb + (size_t)row * CB_DIM;
    float s = 0.f;
    for (int i = tid; i < CB_DIM; i += 128) { float v = r[i]; s += v * v; }
    #pragma unroll
    for (int o = 16; o; o >>= 1) s += __shfl_down_sync(0xffffffffu, s, o);
    if ((tid & 31) == 0) red[tid >> 5] = s;
    __syncthreads();
    float inv = 1.f / fmaxf(sqrtf(red[0] + red[1] + red[2] + red[3]), 1e-12f);
    for (int i = tid; i < CB_DIM; i += 128) {
        float v = r[i] * inv;
        g_cb_nrm[(size_t)row * CB_DIM + i] = v;
        g_cb_bf [(size_t)row * CB_DIM + i] = __float2bfloat16_rn(v);
    }
}

// ---------------- stride-2 conv1d (k=3,pad=1), double-buffered chunks ----------------
template <int CIN, int TIN, int STAGE>
__global__ void __launch_bounds__(256, 2) conv_s2_kernel(const float* __restrict__ xin,
                                                         const float* __restrict__ W) {
    constexpr int TOUT = TIN / 2;
    const float* X = (STAGE == 0) ? xin : (const float*)g_y1;

    __shared__ float Wt[2][24][132];
    __shared__ float Xe[2][8][128];
    __shared__ float Xo[2][8][132];

    int t0  = blockIdx.x * 128;
    int co0 = blockIdx.y * 128;
    int b   = blockIdx.z;
    int tid = threadIdx.x;
    int tx  = tid & 15;
    int ty  = tid >> 4;

    float acc[8][8];
    #pragma unroll
    for (int i = 0; i < 8; i++)
        #pragma unroll
        for (int j = 0; j < 8; j++) acc[i][j] = 0.f;

    const float* Xb = X + (size_t)b * CIN * TIN;

    auto load_chunk = [&](int c0, int p) {
        #pragma unroll
        for (int s = 0; s < 3; s++) {
            int f = tid + s * 256;
            int co = f / 6, q = f % 6;
            float4 w4 = *(const float4*)(W + (size_t)(co0 + co) * (CIN * 3) + c0 * 3 + q * 4);
            Wt[p][q * 4 + 0][co] = w4.x; Wt[p][q * 4 + 1][co] = w4.y;
            Wt[p][q * 4 + 2][co] = w4.z; Wt[p][q * 4 + 3][co] = w4.w;
        }
        #pragma unroll
        for (int s = 0; s < 2; s++) {
            int f = tid + s * 256;
            int ci = f >> 6, u = f & 63;
            float4 x4 = *(const float4*)(Xb + (size_t)(c0 + ci) * TIN + 2 * t0 + u * 4);
            Xe[p][ci][2 * u] = x4.x; Xo[p][ci][2 * u + 1] = x4.y;
            Xe[p][ci][2 * u + 1] = x4.z; Xo[p][ci][2 * u + 2] = x4.w;
        }
        if (tid < 8) {
            float v = 0.f;
            if (t0 > 0) v = Xb[(size_t)(c0 + tid) * TIN + 2 * t0 - 1];
            Xo[p][tid][0] = v;
        }
    };

    load_chunk(0, 0);
    __syncthreads();

    for (int c0 = 0; c0 < CIN; c0 += 8) {
        int buf = (c0 >> 3) & 1;
        if (c0 + 8 < CIN) load_chunk(c0 + 8, buf ^ 1);

        #pragma unroll
        for (int ci = 0; ci < 8; ci++) {
            float xe[8], xoA[5], xoB[5];
            *(float4*)&xe[0]  = *(const float4*)&Xe[buf][ci][tx * 4];
            *(float4*)&xe[4]  = *(const float4*)&Xe[buf][ci][64 + tx * 4];
            *(float4*)&xoA[0] = *(const float4*)&Xo[buf][ci][tx * 4];
            xoA[4] = Xo[buf][ci][tx * 4 + 4];
            *(float4*)&xoB[0] = *(const float4*)&Xo[buf][ci][64 + tx * 4];
            xoB[4] = Xo[buf][ci][64 + tx * 4 + 4];
            #pragma unroll
            for (int k = 0; k < 3; k++) {
                float av[8];
                *(float4*)&av[0] = *(const float4*)&Wt[buf][ci * 3 + k][ty * 4];
                *(float4*)&av[4] = *(const float4*)&Wt[buf][ci * 3 + k][64 + ty * 4];
                #pragma unroll
                for (int i = 0; i < 8; i++)
                    #pragma unroll
                    for (int j = 0; j < 8; j++) {
                        float xv = (j < 4)
                            ? ((k == 0) ? xoA[j] : (k == 1) ? xe[j] : xoA[j + 1])
                            : ((k == 0) ? xoB[j - 4] : (k == 1) ? xe[j] : xoB[j - 3]);
                        acc[i][j] = fmaf(av[i], xv, acc[i][j]);
                    }
            }
        }
        __syncthreads();
    }

    if (STAGE == 0) {
        #pragma unroll
        for (int i = 0; i < 8; i++) {
            int co = co0 + ((i < 4) ? (ty * 4 + i) : (64 + ty * 4 + i - 4));
            float* yr = g_y1 + ((size_t)b * 512 + co) * TOUT + t0;
            *(float4*)(yr + tx * 4)      = make_float4(acc[i][0], acc[i][1], acc[i][2], acc[i][3]);
            *(float4*)(yr + 64 + tx * 4) = make_float4(acc[i][4], acc[i][5], acc[i][6], acc[i][7]);
        }
    } else {
        #pragma unroll
        for (int j = 0; j < 8; j++) {
            int tok = b * TOUT + t0 + ((j < 4) ? (tx * 4 + j) : (64 + tx * 4 + j - 4));
            #pragma unroll
            for (int h = 0; h < 2; h++) {
                int d = co0 + h * 64 + ty * 4;
                float v0 = acc[h * 4 + 0][j], v1 = acc[h * 4 + 1][j];
                float v2 = acc[h * 4 + 2][j], v3 = acc[h * 4 + 3][j];
                *(float4*)(g_encT + (size_t)tok * CB_DIM + d) = make_float4(v0, v1, v2, v3);
                *(__nv_bfloat162*)(g_enc_bf + (size_t)tok * CB_DIM + d)     = __floats2bfloat162_rn(v0, v1);
                *(__nv_bfloat162*)(g_enc_bf + (size_t)tok * CB_DIM + d + 2) = __floats2bfloat162_rn(v2, v3);
            }
        }
    }
}

// ---------------- bf16 mma.sync scoring: k-chunk 64, cp.async 2-stage ----------------
#define A_LD   520
#define B_LD   72
#define SCORE_SMEM ((64 * A_LD + 2 * 128 * B_LD) * 2)

__global__ void __launch_bounds__(256) score_mma_kernel() {
    extern __shared__ __align__(16) __nv_bfloat16 sm[];
    __nv_bfloat16* As = sm;                    // [64][520]
    __nv_bfloat16* Bs = sm + 64 * A_LD;        // [2][128][72]

    int tid = threadIdx.x;
    int warp = tid >> 5, lane = tid & 31;
    int warp_m = warp >> 1;
    int warp_n = warp & 1;
    int mt  = warp_m * 16;
    int wn0 = warp_n * 64;
    int g = lane >> 2, tg = lane & 3;
    int tok0 = blockIdx.x * 64;

    uint32_t as_base = smem_u32(As);
    uint32_t bs_base = smem_u32(Bs);

    // load A: 64 tokens x 512 bf16 (resident)
    #pragma unroll
    for (int s = 0; s < 16; s++) {
        int f = tid + s * 256;
        int t = f >> 6, q = f & 63;
        *(uint4*)(As + t * A_LD + q * 8) =
            ((const uint4*)(g_enc_bf + (size_t)(tok0 + t) * CB_DIM))[q];
    }

    // B chunk issue: 128 codes x 64 bf16 (16 KB) -> 4 cp.async per thread
    auto issue_b = [&](int n0, int kc, int p) {
        uint32_t bdst = bs_base + (uint32_t)(p * 128 * B_LD) * 2u;
        #pragma unroll
        for (int s = 0; s < 4; s++) {
            int f = tid + s * 256;
            int code = f >> 3, q = f & 7;
            cp_async16(bdst + (uint32_t)(code * B_LD + q * 8) * 2u,
                       g_cb_bf + (size_t)(n0 + code) * CB_DIM + kc * 64 + q * 8);
        }
        asm volatile("cp.async.commit_group;" ::: "memory");
    };

    issue_b(0, 0, 0);
    asm volatile("cp.async.wait_group 0;" ::: "memory");
    __syncthreads();

    uint32_t a_row  = (uint32_t)(mt + (lane & 15));
    uint32_t a_koff = (uint32_t)((lane >> 4) << 3);
    uint32_t b_code_off = (uint32_t)(((lane >> 4) << 3) + (lane & 7));
    uint32_t b_koff = (uint32_t)(((lane >> 3) & 1) << 3);

    float tv0[4] = {-3.4e38f, -3.4e38f, -3.4e38f, -3.4e38f};
    float tv1[4] = {-3.4e38f, -3.4e38f, -3.4e38f, -3.4e38f};
    int   ti0[4] = {0x7fffffff, 0x7fffffff, 0x7fffffff, 0x7fffffff};
    int   ti1[4] = {0x7fffffff, 0x7fffffff, 0x7fffffff, 0x7fffffff};

    constexpr int NT = CB_SIZE / 128;
    for (int ntile = 0; ntile < NT; ntile++) {
        int n0 = ntile * 128;

        float c[8][4];
        #pragma unroll
        for (int na = 0; na < 8; na++)
            #pragma unroll
            for (int r = 0; r < 4; r++) c[na][r] = 0.f;

        for (int kc = 0; kc < 8; kc++) {
            int buf = kc & 1;
            if (kc < 7)              issue_b(n0, kc + 1, buf ^ 1);
            else if (ntile + 1 < NT) issue_b(n0 + 128, 0, buf ^ 1);

            uint32_t bbuf = bs_base + (uint32_t)(buf * 128 * B_LD) * 2u;
            #pragma unroll
            for (int ks = 0; ks < 4; ks++) {
                int kb = kc * 64 + ks * 16;
                uint32_t a0, a1, a2, a3;
                uint32_t a_addr = as_base + (a_row * A_LD + (uint32_t)kb + a_koff) * 2u;
                asm volatile("ldmatrix.sync.aligned.m8n8.x4.shared.b16 {%0,%1,%2,%3}, [%4];"
                             : "=r"(a0), "=r"(a1), "=r"(a2), "=r"(a3) : "r"(a_addr));
                #pragma unroll
                for (int pa = 0; pa < 4; pa++) {
                    uint32_t b0, b1, b2, b3;
                    uint32_t code = (uint32_t)(wn0 + pa * 16) + b_code_off;
                    uint32_t b_addr = bbuf + (code * B_LD + (uint32_t)(ks * 16) + b_koff) * 2u;
                    asm volatile("ldmatrix.sync.aligned.m8n8.x4.shared.b16 {%0,%1,%2,%3}, [%4];"
                                 : "=r"(b0), "=r"(b1), "=r"(b2), "=r"(b3) : "r"(b_addr));
                    asm volatile("mma.sync.aligned.m16n8k16.row.col.f32.bf16.bf16.f32 "
                                 "{%0,%1,%2,%3}, {%4,%5,%6,%7}, {%8,%9}, {%0,%1,%2,%3};"
                                 : "+f"(c[pa * 2][0]), "+f"(c[pa * 2][1]),
                                   "+f"(c[pa * 2][2]), "+f"(c[pa * 2][3])
                                 : "r"(a0), "r"(a1), "r"(a2), "r"(a3), "r"(b0), "r"(b1));
                    asm volatile("mma.sync.aligned.m16n8k16.row.col.f32.bf16.bf16.f32 "
                                 "{%0,%1,%2,%3}, {%4,%5,%6,%7}, {%8,%9}, {%0,%1,%2,%3};"
                                 : "+f"(c[pa * 2 + 1][0]), "+f"(c[pa * 2 + 1][1]),
                                   "+f"(c[pa * 2 + 1][2]), "+f"(c[pa * 2 + 1][3])
                                 : "r"(a0), "r"(a1), "r"(a2), "r"(a3), "r"(b2), "r"(b3));
                }
            }
            asm volatile("cp.async.wait_group 0;" ::: "memory");
            __syncthreads();
        }

        // per-row top-2 of this tile, merge across the lane quad
        #pragma unroll
        for (int r = 0; r < 2; r++) {
            float m1 = -3.4e38f, m2 = -3.4e38f;
            int   i1 = 0x7fffffff, i2 = 0x7fffffff;
            #pragma unroll
            for (int na = 0; na < 8; na++) {
                #pragma unroll
                for (int j = 0; j < 2; j++) {
                    float v = c[na][r * 2 + j];
                    int idx = n0 + wn0 + na * 8 + tg * 2 + j;
                    if (v > m1) { m2 = m1; i2 = i1; m1 = v; i1 = idx; }
                    else if (v > m2) { m2 = v; i2 = idx; }
                }
            }
            #pragma unroll
            for (int off = 1; off <= 2; off <<= 1) {
                float om1 = __shfl_xor_sync(0xffffffffu, m1, off);
                int   oi1 = __shfl_xor_sync(0xffffffffu, i1, off);
                float om2 = __shfl_xor_sync(0xffffffffu, m2, off);
                int   oi2 = __shfl_xor_sync(0xffffffffu, i2, off);
                if (better(om1, oi1, m1, i1)) {
                    m2 = m1; i2 = i1;
                    if (better(om2, oi2, m2, i2)) { m2 = om2; i2 = oi2; }
                    m1 = om1; i1 = oi1;
                } else if (better(om1, oi1, m2, i2)) { m2 = om1; i2 = oi1; }
            }
            if (r == 0) { ins4(m1, i1, tv0, ti0); ins4(m2, i2, tv0, ti0); }
            else        { ins4(m1, i1, tv1, ti1); ins4(m2, i2, tv1, ti1); }
        }
    }

    if (tg == 0) {
        int token0 = tok0 + mt + g;
        int token1 = token0 + 8;
        #pragma unroll
        for (int s = 0; s < 4; s++) {
            g_cand[token0 * 8 + warp_n * 4 + s] = ti0[s];
            g_cand[token1 * 8 + warp_n * 4 + s] = ti1[s];
        }
    }
}

// ---------------- exact fp32 rescue over 8 candidates ----------------
__global__ void __launch_bounds__(256) rescue_kernel(float* __restrict__ out) {
    int token = blockIdx.x * 8 + (threadIdx.x >> 5);
    int lane  = threadIdx.x & 31;
    if (token >= NTOK) return;

    const float4* e = (const float4*)(g_encT + (size_t)token * CB_DIM);
    float bestv = -3.4e38f; int besti = 0x7fffffff;
    #pragma unroll
    for (int c = 0; c < 8; c++) {
        int idx = g_cand[token * 8 + c];
        if ((unsigned)idx >= CB_SIZE) continue;
        const float4* cr = (const float4*)(g_cb_nrm + (size_t)idx * CB_DIM);
        float s = 0.f;
        #pragma unroll
        for (int i = 0; i < 4; i++) {
            float4 ev = e[lane + i * 32];
            float4 cv = cr[lane + i * 32];
            s += ev.x * cv.x + ev.y * cv.y + ev.z * cv.z + ev.w * cv.w;
        }
        #pragma unroll
        for (int o = 16; o; o >>= 1) s += __shfl_xor_sync(0xffffffffu, s, o);
        if (s > bestv || (s == bestv && idx < besti)) { bestv = s; besti = idx; }
    }
    if (lane == 0) out[token] = (float)besti;
}

extern "C" void kernel_launch(void* const* d_in, const int* in_sizes, int n_in,
                              void* d_out, int out_size) {
    const float *x = 0, *w1 = 0, *w2 = 0, *cb = 0;
    for (int i = 0; i < n_in; i++) {
        switch (in_sizes[i]) {
            case BATCH * D_IN * T_IN:   x  = (const float*)d_in[i]; break;
            case CB_DIM * D_IN * 3:     w1 = (const float*)d_in[i]; break;
            case CB_DIM * CB_DIM * 3:   w2 = (const float*)d_in[i]; break;
            case CB_SIZE * CB_DIM:      cb = (const float*)d_in[i]; break;
        }
    }
    if (!x || !w1 || !w2 || !cb) {
        x  = (const float*)d_in[0];
        w1 = (const float*)d_in[1];
        w2 = (const float*)d_in[2];
        cb = (const float*)d_in[3];
    }

    cudaFuncSetAttribute(score_mma_kernel,
                         cudaFuncAttributeMaxDynamicSharedMemorySize, SCORE_SMEM);

    cb_norm_kernel<<<CB_SIZE, 128>>>(cb);
    conv_s2_kernel<D_IN, T_IN, 0><<<dim3(T_IN / 256, 4, BATCH), 256>>>(x, w1);
    conv_s2_kernel<CB_DIM, T1, 1><<<dim3(T1 / 256, 4, BATCH), 256>>>(nullptr, w2);
    score_mma_kernel<<<NTOK / 64, 256, SCORE_SMEM>>>();
    rescue_kernel<<<(NTOK + 7) / 8, 256>>>((float*)d_out);
}